// round 2
// baseline (speedup 1.0000x reference)
#include <cuda_runtime.h>
#include <cstdint>

// Perception3D: 7-point stencil, 5 output groups per input channel.
// in : [B=4, C=16, D=64, H=64, W=64] fp32
// out: [B=4, C*G=80, D=64, H=64, W=64] fp32, out[b, c*5+g, ...]
//   g=0 ident, g=1 6-neighbor sum, g=2 gx (xp-xm), g=3 gy, g=4 gz
// Each thread processes TWO consecutive h-rows (same d, same w4 quad):
// y-taps overlap between the rows, so 8 float4 loads serve 2 outputs
// (vs 10 for independent threads), and per-thread MLP doubles.

#define Dz 64
#define Hy 64
#define Wx 64
#define PLANE (Dz * Hy * Wx)      // 262144 elems per (b,c) volume
#define ROW   Wx                  // 64
#define SLAB  (Hy * Wx)           // 4096
#define W4 (Wx / 4)               // 16 float4 per row
#define G 5

#define F4Z make_float4(0.f, 0.f, 0.f, 0.f)

__device__ __forceinline__ float4 ld4(const float* p) {
    return *reinterpret_cast<const float4*>(p);
}

__global__ void __launch_bounds__(256)
perception3d_kernel(const float* __restrict__ in, float* __restrict__ out) {
    // tid over BC * D * (H/2) * W4 = 64*64*32*16 = 2,097,152
    unsigned tid = blockIdx.x * blockDim.x + threadIdx.x;

    unsigned w4 = tid & (W4 - 1);          // 0..15
    unsigned hh = (tid >> 4) & 31;         // 0..31  (h pair index)
    unsigned d  = (tid >> 9) & (Dz - 1);   // 0..63
    unsigned bc = tid >> 15;               // 0..63

    unsigned h0 = hh * 2;                  // even row
    const float* r0 = in + (size_t)bc * PLANE + (size_t)d * SLAB + (size_t)h0 * ROW + (size_t)w4 * 4;
    const float* r1 = r0 + ROW;

    // Centers
    float4 c0 = ld4(r0);
    float4 c1 = ld4(r1);

    // y taps: ym0 = row h0-1, yp0 = c1; ym1 = c0, yp1 = row h0+2
    float4 ym0 = (hh >= 1) ? ld4(r0 - ROW) : F4Z;
    float4 yp1 = (hh < 31) ? ld4(r1 + ROW) : F4Z;

    // x taps (depth ±SLAB) for both rows
    float4 xp0 = (d + 1 < Dz) ? ld4(r0 + SLAB) : F4Z;
    float4 xm0 = (d >= 1)     ? ld4(r0 - SLAB) : F4Z;
    float4 xp1 = (d + 1 < Dz) ? ld4(r1 + SLAB) : F4Z;
    float4 xm1 = (d >= 1)     ? ld4(r1 - SLAB) : F4Z;

    // z edges (within row)
    float n0 = (w4 < W4 - 1) ? r0[4]  : 0.f;
    float p0 = (w4 >= 1)     ? r0[-1] : 0.f;
    float n1 = (w4 < W4 - 1) ? r1[4]  : 0.f;
    float p1 = (w4 >= 1)     ? r1[-1] : 0.f;

    float4 zp0 = make_float4(c0.y, c0.z, c0.w, n0);
    float4 zm0 = make_float4(p0, c0.x, c0.y, c0.z);
    float4 zp1 = make_float4(c1.y, c1.z, c1.w, n1);
    float4 zm1 = make_float4(p1, c1.x, c1.y, c1.z);

    // Row 0 groups
    float4 ns0, gx0, gy0, gz0;
    ns0.x = xp0.x + xm0.x + c1.x + ym0.x + zp0.x + zm0.x;
    ns0.y = xp0.y + xm0.y + c1.y + ym0.y + zp0.y + zm0.y;
    ns0.z = xp0.z + xm0.z + c1.z + ym0.z + zp0.z + zm0.z;
    ns0.w = xp0.w + xm0.w + c1.w + ym0.w + zp0.w + zm0.w;
    gx0.x = xp0.x - xm0.x; gx0.y = xp0.y - xm0.y; gx0.z = xp0.z - xm0.z; gx0.w = xp0.w - xm0.w;
    gy0.x = c1.x - ym0.x;  gy0.y = c1.y - ym0.y;  gy0.z = c1.z - ym0.z;  gy0.w = c1.w - ym0.w;
    gz0.x = zp0.x - zm0.x; gz0.y = zp0.y - zm0.y; gz0.z = zp0.z - zm0.z; gz0.w = zp0.w - zm0.w;

    // Row 1 groups (yp1 = loaded row, ym1 = c0)
    float4 ns1, gx1, gy1, gz1;
    ns1.x = xp1.x + xm1.x + yp1.x + c0.x + zp1.x + zm1.x;
    ns1.y = xp1.y + xm1.y + yp1.y + c0.y + zp1.y + zm1.y;
    ns1.z = xp1.z + xm1.z + yp1.z + c0.z + zp1.z + zm1.z;
    ns1.w = xp1.w + xm1.w + yp1.w + c0.w + zp1.w + zm1.w;
    gx1.x = xp1.x - xm1.x; gx1.y = xp1.y - xm1.y; gx1.z = xp1.z - xm1.z; gx1.w = xp1.w - xm1.w;
    gy1.x = yp1.x - c0.x;  gy1.y = yp1.y - c0.y;  gy1.z = yp1.z - c0.z;  gy1.w = yp1.w - c0.w;
    gz1.x = zp1.x - zm1.x; gz1.y = zp1.y - zm1.y; gz1.z = zp1.z - zm1.z; gz1.w = zp1.w - zm1.w;

    // Output addressing
    unsigned b  = bc >> 4;
    unsigned cc = bc & 15;
    size_t spatial0 = (size_t)d * SLAB + (size_t)h0 * ROW + (size_t)w4 * 4;
    float* ob = out + (size_t)b * (16 * G * PLANE) + (size_t)(cc * G) * PLANE + spatial0;

    // Streaming stores — output is never re-read
    __stcs(reinterpret_cast<float4*>(ob),                 c0);
    __stcs(reinterpret_cast<float4*>(ob + ROW),           c1);
    __stcs(reinterpret_cast<float4*>(ob + 1 * PLANE),       ns0);
    __stcs(reinterpret_cast<float4*>(ob + 1 * PLANE + ROW), ns1);
    __stcs(reinterpret_cast<float4*>(ob + 2 * PLANE),       gx0);
    __stcs(reinterpret_cast<float4*>(ob + 2 * PLANE + ROW), gx1);
    __stcs(reinterpret_cast<float4*>(ob + 3 * PLANE),       gy0);
    __stcs(reinterpret_cast<float4*>(ob + 3 * PLANE + ROW), gy1);
    __stcs(reinterpret_cast<float4*>(ob + 4 * PLANE),       gz0);
    __stcs(reinterpret_cast<float4*>(ob + 4 * PLANE + ROW), gz1);
}

extern "C" void kernel_launch(void* const* d_in, const int* in_sizes, int n_in,
                              void* d_out, int out_size) {
    const float* in = (const float*)d_in[0];
    float* out = (float*)d_out;
    // 2,097,152 threads / 256 = 8192 blocks
    perception3d_kernel<<<8192, 256>>>(in, out);
}